// round 15
// baseline (speedup 1.0000x reference)
#include <cuda_runtime.h>
#include <mma.h>
#include <cstdint>
#include <cstddef>

using namespace nvcuda;

// Problem dims
#define B_ 4
#define S_ 2048
#define DM_ 512
#define DA_ 512
#define H_ 8
#define F_ 4
#define DEP_ 64
#define BS_ (B_ * S_)         // 8192
#define ROWS_ (B_ * H_ * S_)  // 65536

// ---------------- scratch (no allocations allowed) ----------------
__device__ float g_qp[(size_t)BS_ * DA_];
__device__ float g_kp[(size_t)BS_ * DA_];
__device__ float g_vp[(size_t)BS_ * DA_];
__device__ float g_xs[(size_t)BS_ * (H_ * F_)];
__device__ float g_ctx[(size_t)BS_ * DA_];
__device__ float g_psum[(size_t)ROWS_ * 128];
__device__ float g_rinv[(size_t)ROWS_];

typedef wmma::fragment<wmma::matrix_a, 16, 16, 8, wmma::precision::tf32, wmma::row_major> FragA;
typedef wmma::fragment<wmma::matrix_b, 16, 16, 8, wmma::precision::tf32, wmma::row_major> FragB;
typedef wmma::fragment<wmma::matrix_b, 16, 16, 8, wmma::precision::tf32, wmma::col_major> FragBc;
typedef wmma::fragment<wmma::accumulator, 16, 16, 8, float> FragC;

template <typename F>
__device__ __forceinline__ void cvt_tf32(F& f) {
#pragma unroll
    for (int i = 0; i < f.num_elements; i++)
        f.x[i] = wmma::__float_to_tf32(f.x[i]);
}

// ---------------- cp.async helpers ----------------
__device__ __forceinline__ void cp16(float* dst_smem, const float* src_g) {
    uint32_t d = (uint32_t)__cvta_generic_to_shared(dst_smem);
    asm volatile("cp.async.cg.shared.global [%0], [%1], 16;"
                 :: "r"(d), "l"(src_g) : "memory");
}
__device__ __forceinline__ void cp_commit() {
    asm volatile("cp.async.commit_group;" ::: "memory");
}
template <int N>
__device__ __forceinline__ void cp_wait() {
    asm volatile("cp.async.wait_group %0;" :: "n"(N) : "memory");
}

// =================================================================
// Shared GEMM device body: C[M,N] = A[M,K] @ W[K,N] + bias[N]
// block tile BM x BN, BK=32, 3-stage cp.async ring, 256 threads.
// SINGLE __syncthreads per K-iteration: sync at top of iter c proves
// (a) stage c data visible, (b) compute(c-1) done for all warps, so
// loads for c+2 (same stage as c-1) may be issued after it.
// =================================================================
template <int BM, int BN, int WR, int WC>
__device__ __forceinline__ void gemm_body(
    const float* __restrict__ A, const float* __restrict__ W,
    const float* __restrict__ bias, float* __restrict__ C,
    int M, int N, int K, int m0, int n0, float* sm)
{
    constexpr int LDA = 36;
    constexpr int LDB = BN + 4;
    constexpr int SA  = BM * LDA;
    constexpr int SW  = 32 * LDB;
    constexpr int MI = BM / (WR * 16);
    constexpr int NI = BN / (WC * 16);

    float* Cs = sm;

    const int tid = threadIdx.x;
    const int wid = tid >> 5;
    const int warp_m = wid % WR;
    const int warp_n = wid / WR;
    const int nc = K / 32;

    auto loadStage = [&](int st, int c) {
        float* As = sm + st * SA;
        float* Ws = sm + 3 * SA + st * SW;
#pragma unroll
        for (int r = 0; r < BM / 32; r++) {
            int idx = tid + 256 * r;
            int m = idx >> 3, k4 = (idx & 7) * 4;
            cp16(&As[m * LDA + k4], &A[(size_t)(m0 + m) * K + c * 32 + k4]);
        }
#pragma unroll
        for (int r = 0; r < BN / 32; r++) {
            int idx = tid + 256 * r;
            int kk = idx / (BN / 4), n4 = (idx % (BN / 4)) * 4;
            cp16(&Ws[kk * LDB + n4], &W[(size_t)(c * 32 + kk) * N + n0 + n4]);
        }
    };

    FragC acc[MI][NI];
#pragma unroll
    for (int i = 0; i < MI; i++)
#pragma unroll
        for (int j = 0; j < NI; j++) wmma::fill_fragment(acc[i][j], 0.0f);

    loadStage(0, 0); cp_commit();
    loadStage(1, 1); cp_commit();

    for (int c = 0; c < nc; c++) {
        if (c + 1 < nc) cp_wait<1>(); else cp_wait<0>();
        __syncthreads();                       // stage c visible; compute(c-1) done
        if (c + 2 < nc) {
            loadStage((c + 2) % 3, c + 2);     // overwrites stage used by compute(c-1)
            cp_commit();
        }

        const float* As = sm + (c % 3) * SA;
        const float* Ws = sm + 3 * SA + (c % 3) * SW;
#pragma unroll
        for (int ds = 0; ds < 4; ds++) {
            FragA af[MI];
#pragma unroll
            for (int i = 0; i < MI; i++) {
                wmma::load_matrix_sync(af[i],
                    &As[(warp_m * (BM / WR) + i * 16) * LDA + ds * 8], LDA);
                cvt_tf32(af[i]);
            }
            FragB bf;
#pragma unroll
            for (int j = 0; j < NI; j++) {
                wmma::load_matrix_sync(bf,
                    &Ws[ds * 8 * LDB + warp_n * (BN / WC) + j * 16], LDB);
                cvt_tf32(bf);
#pragma unroll
                for (int i = 0; i < MI; i++)
                    wmma::mma_sync(acc[i][j], af[i], bf, acc[i][j]);
            }
        }
    }

    // epilogue (Cs aliases stage smem: sync before overwrite)
    __syncthreads();
#pragma unroll
    for (int i = 0; i < MI; i++)
#pragma unroll
        for (int j = 0; j < NI; j++)
            wmma::store_matrix_sync(
                &Cs[(warp_m * (BM / WR) + i * 16) * LDB +
                    warp_n * (BN / WC) + j * 16],
                acc[i][j], LDB, wmma::mem_row_major);
    __syncthreads();

#pragma unroll
    for (int r = 0; r < BM * BN / 1024; r++) {
        int idx = tid + 256 * r;
        int m = idx / (BN / 4), n4 = (idx % (BN / 4)) * 4;
        float4 v = *(float4*)&Cs[m * LDB + n4];
        float4 bz = *(const float4*)&bias[n0 + n4];
        v.x += bz.x; v.y += bz.y; v.z += bz.z; v.w += bz.w;
        *(float4*)&C[(size_t)(m0 + m) * N + n0 + n4] = v;
    }
}

template <int BM, int BN, int WR, int WC>
__global__ __launch_bounds__(256) void gemm_wmma(
    const float* __restrict__ A, const float* __restrict__ W,
    const float* __restrict__ bias, float* __restrict__ C,
    int M, int N, int K)
{
    extern __shared__ float sm[];
    gemm_body<BM, BN, WR, WC>(A, W, bias, C, M, N, K,
                              blockIdx.y * BM, blockIdx.x * BN, sm);
}

// Batched Q/K/V projection: blockIdx.z selects the matrix set.
__global__ __launch_bounds__(256) void gemm_qkv_wmma(
    const float* __restrict__ q,  const float* __restrict__ k,
    const float* __restrict__ v,
    const float* __restrict__ wq, const float* __restrict__ wk,
    const float* __restrict__ wv,
    const float* __restrict__ bq, const float* __restrict__ bk,
    const float* __restrict__ bv,
    float* __restrict__ qp, float* __restrict__ kp, float* __restrict__ vp)
{
    extern __shared__ float sm[];
    const float *A, *W, *bias;
    float* C;
    if (blockIdx.z == 0)      { A = q; W = wq; bias = bq; C = qp; }
    else if (blockIdx.z == 1) { A = k; W = wk; bias = bk; C = kp; }
    else                      { A = v; W = wv; bias = bv; C = vp; }
    gemm_body<64, 128, 2, 4>(A, W, bias, C, BS_, DA_, DM_,
                             blockIdx.y * 64, blockIdx.x * 128, sm);
}

// =================================================================
// Logits+exp: 256 threads, 64q x 32k tiles, pipelined across heads,
// ONE __syncthreads per head. xdiff in registers (head-invariant).
// smem: Qt[2][64*68] Kt[2][32*68] xw[2048] Ls[8][320] = 70656 B.
// =================================================================
#define LOG_SMEM_BYTES 70656

__global__ __launch_bounds__(256, 3) void logits_exp_wmma(
    const float* __restrict__ qp, const float* __restrict__ kp,
    const float* __restrict__ xs, const float* __restrict__ xdiff,
    float* __restrict__ attn, float* __restrict__ psum)
{
    constexpr int SQ = 64 * 68;   // 4352
    constexpr int SK = 32 * 68;   // 2176

    extern __shared__ float sm[];
    float* QtB = sm;                     // 2 stages
    float* KtB = sm + 2 * SQ;            // 2 stages
    float* xw  = sm + 2 * SQ + 2 * SK;   // 2048
    float* LsB = xw + 2048;              // 8 x 320

    const int tid  = threadIdx.x;
    const int w    = tid >> 5;
    const int lane = tid & 31;
    const int wq   = w & 3;     // q-group (16 rows)
    const int wkh  = w >> 2;    // k-half (16 cols)
    const int b  = blockIdx.z;
    const int q0 = blockIdx.y * 64;
    const int k0 = blockIdx.x * 32;
    float* Ls = LsB + w * 320;  // private 16x20

    auto loadQK = [&](int st, int h) {
        float* Qt = QtB + st * SQ;
        float* Kt = KtB + st * SK;
#pragma unroll
        for (int r = 0; r < 4; r++) {
            int idx = tid + 256 * r;
            int qi = idx >> 4, d4 = (idx & 15) * 4;
            cp16(&Qt[qi * 68 + d4],
                 &qp[(size_t)(b * S_ + q0 + qi) * DA_ + h * DEP_ + d4]);
        }
#pragma unroll
        for (int r = 0; r < 2; r++) {
            int idx = tid + 256 * r;
            int kk = idx >> 4, d4 = (idx & 15) * 4;
            cp16(&Kt[kk * 68 + d4],
                 &kp[(size_t)(b * S_ + k0 + kk) * DA_ + h * DEP_ + d4]);
        }
    };

    // xw tile (one-time, with head-0 group)
#pragma unroll
    for (int r = 0; r < 2; r++) {
        int idx = tid + 256 * r;
        int qi = idx >> 3, c4 = (idx & 7) * 4;
        cp16(&xw[qi * 32 + c4], &xs[(size_t)(b * S_ + q0 + qi) * 32 + c4]);
    }
    loadQK(0, 0);
    cp_commit();

    // xdiff -> registers (head-invariant per-thread mapping)
    float4 xdr[2][4];
    const float4* xdg = (const float4*)xdiff;
#pragma unroll
    for (int r = 0; r < 2; r++) {
        int idx = lane + 32 * r;
        int qi = idx >> 2, g = idx & 3;
        int qrow = wq * 16 + qi;
        int fcol = wkh * 16 + g * 4;
        const float4* src = &xdg[((size_t)(b * S_ + q0 + qrow)) * S_ + k0 + fcol];
#pragma unroll
        for (int t = 0; t < 4; t++) xdr[r][t] = src[t];
    }

    for (int h = 0; h < H_; h++) {
        cp_wait<0>();                    // stage h's loads complete
        __syncthreads();                 // visible + compute(h-1) done everywhere
        if (h + 1 < H_) {
            loadQK((h + 1) & 1, h + 1);  // overwrites stage used by compute(h-1)
            cp_commit();
        }

        float* Qt = QtB + (h & 1) * SQ;
        float* Kt = KtB + (h & 1) * SK;

        FragC acc;
        wmma::fill_fragment(acc, 0.0f);
#pragma unroll
        for (int ds = 0; ds < 8; ds++) {
            FragA a;
            wmma::load_matrix_sync(a, &Qt[(wq * 16) * 68 + ds * 8], 68);
            cvt_tf32(a);
            FragBc bf;
            wmma::load_matrix_sync(bf, &Kt[(wkh * 16) * 68 + ds * 8], 68);
            cvt_tf32(bf);
            wmma::mma_sync(acc, a, bf, acc);
        }

        wmma::store_matrix_sync(Ls, acc, 20, wmma::mem_row_major);
        __syncwarp();

#pragma unroll
        for (int r = 0; r < 2; r++) {
            int idx = lane + 32 * r;
            int qi = idx >> 2;
            int g  = idx & 3;
            int qrow = wq * 16 + qi;
            int fcol = wkh * 16 + g * 4;
            float4 lv = *(float4*)&Ls[qi * 20 + g * 4];
            float4 xh = *(float4*)&xw[qrow * 32 + h * 4];
            float e[4];
            float* lp = &lv.x;
            float tsum = 0.0f;
#pragma unroll
            for (int t = 0; t < 4; t++) {
                float4 xv = xdr[r][t];
                float bias = xv.x * xh.x + xv.y * xh.y + xv.z * xh.z + xv.w * xh.w;
                e[t] = __expf(lp[t] * 0.125f + bias * 0.5f);
                tsum += e[t];
            }
            size_t row_g = (size_t)(b * H_ + h) * S_ + q0 + qrow;
            *(float4*)&attn[row_g * S_ + k0 + fcol] =
                make_float4(e[0], e[1], e[2], e[3]);
            tsum += __shfl_down_sync(0xffffffffu, tsum, 2, 4);
            tsum += __shfl_down_sync(0xffffffffu, tsum, 1, 4);
            if ((lane & 3) == 0)
                psum[row_g * 128 + blockIdx.x * 2 + wkh] = tsum;
        }
    }
}

// =================================================================
// Row-sum reduce: g_rinv[row] = 1 / sum(g_psum[row][0..127])
// =================================================================
__global__ __launch_bounds__(256) void rowsum_kernel(
    const float* __restrict__ psum, float* __restrict__ rinv)
{
    const int wir  = threadIdx.x >> 5;
    const int lane = threadIdx.x & 31;
    const size_t row = (size_t)blockIdx.x * 8 + wir;
    const float* p = psum + row * 128;
    float s = (p[lane] + p[lane + 32]) + (p[lane + 64] + p[lane + 96]);
#pragma unroll
    for (int o = 16; o > 0; o >>= 1) s += __shfl_xor_sync(0xffffffffu, s, o);
    if (lane == 0) rinv[row] = 1.0f / s;
}

// =================================================================
// PV, 3-stage ring, 64q tiles, ONE __syncthreads per chunk:
// ctx = (e @ V) * rinv ; writes p = e*rinv back to attn in place.
// Block = (64q, bh), BK=32.
// =================================================================
#define PV_SMEM_BYTES 54016

__global__ __launch_bounds__(256) void pv_wmma(
    float* __restrict__ attn, const float* __restrict__ vp,
    const float* __restrict__ rinv, float* __restrict__ ctx)
{
    constexpr int SA = 64 * 36;   // 2304
    constexpr int SV = 32 * 68;   // 2176

    extern __shared__ float sm[];
    float* AtB = sm;
    float* VtB = sm + 3 * SA;
    float* rs  = sm + 3 * SA + 3 * SV;   // [64]
    float* Cs  = sm;                     // epilogue reuse

    const int tid = threadIdx.x;
    const int w   = tid >> 5;
    const int wq  = w & 3;
    const int wd  = w >> 2;
    const int bh  = blockIdx.y;
    const int b   = bh >> 3, h = bh & 7;
    const int q0  = blockIdx.x * 64;
    const int nc  = S_ / 32;

    if (tid < 64) rs[tid] = rinv[(size_t)bh * S_ + q0 + tid];

    auto loadChunk = [&](int st, int c) {
        float* At = AtB + st * SA;
        float* Vt = VtB + st * SV;
#pragma unroll
        for (int r = 0; r < 2; r++) {
            int idx = tid + 256 * r;
            int qi = idx >> 3, k4 = (idx & 7) * 4;
            cp16(&At[qi * 36 + k4],
                 &attn[((size_t)bh * S_ + q0 + qi) * S_ + c * 32 + k4]);
        }
#pragma unroll
        for (int r = 0; r < 2; r++) {
            int idx = tid + 256 * r;
            int kk = idx >> 4, d4 = (idx & 15) * 4;
            cp16(&Vt[kk * 68 + d4],
                 &vp[(size_t)(b * S_ + c * 32 + kk) * DA_ + h * DEP_ + d4]);
        }
    };

    FragC acc[2];
#pragma unroll
    for (int j = 0; j < 2; j++) wmma::fill_fragment(acc[j], 0.0f);

    loadChunk(0, 0); cp_commit();
    loadChunk(1, 1); cp_commit();

    for (int c = 0; c < nc; c++) {
        if (c + 1 < nc) cp_wait<1>(); else cp_wait<0>();
        __syncthreads();                    // stage c visible; compute(c-1) done
        if (c + 2 < nc) {
            loadChunk((c + 2) % 3, c + 2);  // overwrites stage used by compute(c-1)
            cp_commit();
        }

        const float* At = AtB + (c % 3) * SA;
        const float* Vt = VtB + (c % 3) * SV;

        // write p = e * rinv back to attn
#pragma unroll
        for (int r = 0; r < 2; r++) {
            int idx = tid + 256 * r;
            int qi = idx >> 3, k4 = (idx & 7) * 4;
            float4 v = *(const float4*)&At[qi * 36 + k4];
            float riv = rs[qi];
            v.x *= riv; v.y *= riv; v.z *= riv; v.w *= riv;
            *(float4*)&attn[((size_t)bh * S_ + q0 + qi) * S_ + c * 32 + k4] = v;
        }

#pragma unroll
        for (int ds = 0; ds < 4; ds++) {
            FragA a;
            wmma::load_matrix_sync(a, &At[(wq * 16) * 36 + ds * 8], 36);
            cvt_tf32(a);
#pragma unroll
            for (int j = 0; j < 2; j++) {
                FragB bf;
                wmma::load_matrix_sync(bf, &Vt[ds * 8 * 68 + wd * 32 + j * 16], 68);
                cvt_tf32(bf);
                wmma::mma_sync(acc[j], a, bf, acc[j]);
            }
        }
    }

    // epilogue: stage in smem (aliases AtB -> sync first), scale, store
    __syncthreads();
#pragma unroll
    for (int j = 0; j < 2; j++)
        wmma::store_matrix_sync(&Cs[(wq * 16) * 68 + wd * 32 + j * 16],
                                acc[j], 68, wmma::mem_row_major);
    __syncthreads();

#pragma unroll
    for (int r = 0; r < 4; r++) {
        int idx = tid + 256 * r;
        int qi = idx >> 4, d4 = (idx & 15) * 4;
        float4 v = *(float4*)&Cs[qi * 68 + d4];
        float riv = rs[qi];
        v.x *= riv; v.y *= riv; v.z *= riv; v.w *= riv;
        *(float4*)&ctx[(size_t)(b * S_ + q0 + qi) * DA_ + h * DEP_ + d4] = v;
    }
}

// =================================================================
extern "C" void kernel_launch(void* const* d_in, const int* in_sizes, int n_in,
                              void* d_out, int out_size)
{
    const float* q     = (const float*)d_in[0];
    const float* k     = (const float*)d_in[1];
    const float* v     = (const float*)d_in[2];
    const float* xdiff = (const float*)d_in[3];
    const float* wq    = (const float*)d_in[4];
    const float* bq    = (const float*)d_in[5];
    const float* wk    = (const float*)d_in[6];
    const float* bk    = (const float*)d_in[7];
    const float* wv    = (const float*)d_in[8];
    const float* bv    = (const float*)d_in[9];
    const float* wx    = (const float*)d_in[10];
    const float* bx    = (const float*)d_in[11];
    const float* wo    = (const float*)d_in[12];
    const float* bo    = (const float*)d_in[13];

    float* out  = (float*)d_out;                        // [B,S,DM]
    float* attn = out + (size_t)BS_ * DM_;              // [B,H,S,S]

    float *qp, *kp, *vp, *xs, *ctx, *psum, *rinv;
    cudaGetSymbolAddress((void**)&qp,   g_qp);
    cudaGetSymbolAddress((void**)&kp,   g_kp);
    cudaGetSymbolAddress((void**)&vp,   g_vp);
    cudaGetSymbolAddress((void**)&xs,   g_xs);
    cudaGetSymbolAddress((void**)&ctx,  g_ctx);
    cudaGetSymbolAddress((void**)&psum, g_psum);
    cudaGetSymbolAddress((void**)&rinv, g_rinv);

    const int SM_G128 = (3 * 64 * 36 + 3 * 32 * 132) * 4;    // 78336
    const int SM_G32  = (3 * 64 * 36 + 3 * 32 * 36) * 4;     // 41472
    const int SM_LOG  = LOG_SMEM_BYTES;                      // 70656
    const int SM_PV   = PV_SMEM_BYTES;                       // 54016

    cudaFuncSetAttribute((const void*)gemm_qkv_wmma,
                         cudaFuncAttributeMaxDynamicSharedMemorySize, SM_G128);
    cudaFuncSetAttribute((const void*)gemm_wmma<64, 128, 2, 4>,
                         cudaFuncAttributeMaxDynamicSharedMemorySize, SM_G128);
    cudaFuncSetAttribute((const void*)gemm_wmma<64, 32, 4, 2>,
                         cudaFuncAttributeMaxDynamicSharedMemorySize, SM_G32);
    cudaFuncSetAttribute((const void*)logits_exp_wmma,
                         cudaFuncAttributeMaxDynamicSharedMemorySize, SM_LOG);
    cudaFuncSetAttribute((const void*)pv_wmma,
                         cudaFuncAttributeMaxDynamicSharedMemorySize, SM_PV);

    // Q/K/V projections — one batched launch
    gemm_qkv_wmma<<<dim3(DA_ / 128, BS_ / 64, 3), 256, SM_G128>>>(
        q, k, v, wq, wk, wv, bq, bk, bv, qp, kp, vp);

    // x = qp @ wx + bx
    gemm_wmma<64, 32, 4, 2><<<dim3(1, BS_ / 64), 256, SM_G32>>>(
        qp, wx, bx, xs, BS_, H_ * F_, DA_);

    // logits + bias + exp -> attn (unnormalized) + partial sums
    logits_exp_wmma<<<dim3(S_ / 32, S_ / 64, B_), 256, SM_LOG>>>(
        qp, kp, xs, xdiff, attn, psum);

    // rowsum -> 1/s
    rowsum_kernel<<<ROWS_ / 8, 256>>>(psum, rinv);

    // PV + in-place normalization of attn
    pv_wmma<<<dim3(S_ / 64, B_ * H_), 256, SM_PV>>>(attn, vp, rinv, ctx);

    // out = ctx @ wo + bo
    gemm_wmma<64, 128, 2, 4><<<dim3(DM_ / 128, BS_ / 64), 256, SM_G128>>>(
        ctx, wo, bo, out, BS_, DM_, DA_);
}

// round 16
// speedup vs baseline: 1.0756x; 1.0756x over previous
#include <cuda_runtime.h>
#include <mma.h>
#include <cstdint>
#include <cstddef>

using namespace nvcuda;

// Problem dims
#define B_ 4
#define S_ 2048
#define DM_ 512
#define DA_ 512
#define H_ 8
#define F_ 4
#define DEP_ 64
#define BS_ (B_ * S_)         // 8192
#define ROWS_ (B_ * H_ * S_)  // 65536

// ---------------- scratch (no allocations allowed) ----------------
__device__ float g_qp[(size_t)BS_ * DA_];
__device__ float g_kp[(size_t)BS_ * DA_];
__device__ float g_vp[(size_t)BS_ * DA_];
__device__ float g_xs[(size_t)BS_ * (H_ * F_)];
__device__ float g_ctx[(size_t)BS_ * DA_];
__device__ float g_psum[(size_t)ROWS_ * 128];
__device__ float g_rinv[(size_t)ROWS_];

typedef wmma::fragment<wmma::matrix_a, 16, 16, 8, wmma::precision::tf32, wmma::row_major> FragA;
typedef wmma::fragment<wmma::matrix_b, 16, 16, 8, wmma::precision::tf32, wmma::row_major> FragB;
typedef wmma::fragment<wmma::matrix_b, 16, 16, 8, wmma::precision::tf32, wmma::col_major> FragBc;
typedef wmma::fragment<wmma::accumulator, 16, 16, 8, float> FragC;

template <typename F>
__device__ __forceinline__ void cvt_tf32(F& f) {
#pragma unroll
    for (int i = 0; i < f.num_elements; i++)
        f.x[i] = wmma::__float_to_tf32(f.x[i]);
}

// ---------------- cp.async helpers ----------------
__device__ __forceinline__ void cp16(float* dst_smem, const float* src_g) {
    uint32_t d = (uint32_t)__cvta_generic_to_shared(dst_smem);
    asm volatile("cp.async.cg.shared.global [%0], [%1], 16;"
                 :: "r"(d), "l"(src_g) : "memory");
}
__device__ __forceinline__ void cp_commit() {
    asm volatile("cp.async.commit_group;" ::: "memory");
}
template <int N>
__device__ __forceinline__ void cp_wait() {
    asm volatile("cp.async.wait_group %0;" :: "n"(N) : "memory");
}

// =================================================================
// Shared GEMM device body (R14 pipeline ordering):
// C[M,N] = A[M,K] @ W[K,N] + bias[N]; BM x BN tile, BK=32, 3-stage.
// Bias pre-loaded into accumulator fragments; epilogue stores the
// accumulators DIRECTLY to global (no smem staging, no extra syncs).
// =================================================================
template <int BM, int BN, int WR, int WC>
__device__ __forceinline__ void gemm_body(
    const float* __restrict__ A, const float* __restrict__ W,
    const float* __restrict__ bias, float* __restrict__ C,
    int M, int N, int K, int m0, int n0, float* sm)
{
    constexpr int LDA = 36;
    constexpr int LDB = BN + 4;
    constexpr int SA  = BM * LDA;
    constexpr int SW  = 32 * LDB;
    constexpr int MI = BM / (WR * 16);
    constexpr int NI = BN / (WC * 16);

    const int tid = threadIdx.x;
    const int wid = tid >> 5;
    const int warp_m = wid % WR;
    const int warp_n = wid / WR;
    const int nc = K / 32;

    // ---- bias -> accumulator fragments (once, before stage preload) ----
    FragC acc[MI][NI];
    {
        float* bs = sm;   // 16 rows x BN, stride LDB (reuses stage area)
        for (int idx = tid; idx < 4 * BN; idx += 256) {   // 16*BN/4 float4
            int row = idx / (BN / 4), n4 = (idx % (BN / 4)) * 4;
            *(float4*)&bs[row * LDB + n4] = *(const float4*)&bias[n0 + n4];
        }
        __syncthreads();
#pragma unroll
        for (int j = 0; j < NI; j++)
            wmma::load_matrix_sync(acc[0][j],
                &bs[warp_n * (BN / WC) + j * 16], LDB, wmma::mem_row_major);
#pragma unroll
        for (int i = 1; i < MI; i++)
#pragma unroll
            for (int j = 0; j < NI; j++) acc[i][j] = acc[0][j];
        __syncthreads();   // before stage preloads overwrite bs
    }

    auto loadStage = [&](int st, int c) {
        float* As = sm + st * SA;
        float* Ws = sm + 3 * SA + st * SW;
#pragma unroll
        for (int r = 0; r < BM / 32; r++) {
            int idx = tid + 256 * r;
            int m = idx >> 3, k4 = (idx & 7) * 4;
            cp16(&As[m * LDA + k4], &A[(size_t)(m0 + m) * K + c * 32 + k4]);
        }
#pragma unroll
        for (int r = 0; r < BN / 32; r++) {
            int idx = tid + 256 * r;
            int kk = idx / (BN / 4), n4 = (idx % (BN / 4)) * 4;
            cp16(&Ws[kk * LDB + n4], &W[(size_t)(c * 32 + kk) * N + n0 + n4]);
        }
    };

    loadStage(0, 0); cp_commit();
    loadStage(1, 1); cp_commit();

    for (int c = 0; c < nc; c++) {
        if (c + 2 < nc) {
            loadStage((c + 2) % 3, c + 2);
            cp_commit();
            cp_wait<2>();
        } else if (c + 1 < nc) {
            cp_wait<1>();
        } else {
            cp_wait<0>();
        }
        __syncthreads();

        const float* As = sm + (c % 3) * SA;
        const float* Ws = sm + 3 * SA + (c % 3) * SW;
#pragma unroll
        for (int ds = 0; ds < 4; ds++) {
            FragA af[MI];
#pragma unroll
            for (int i = 0; i < MI; i++) {
                wmma::load_matrix_sync(af[i],
                    &As[(warp_m * (BM / WR) + i * 16) * LDA + ds * 8], LDA);
                cvt_tf32(af[i]);
            }
            FragB bf;
#pragma unroll
            for (int j = 0; j < NI; j++) {
                wmma::load_matrix_sync(bf,
                    &Ws[ds * 8 * LDB + warp_n * (BN / WC) + j * 16], LDB);
                cvt_tf32(bf);
#pragma unroll
                for (int i = 0; i < MI; i++)
                    wmma::mma_sync(acc[i][j], af[i], bf, acc[i][j]);
            }
        }
        __syncthreads();
    }

    // epilogue: store accumulators (bias already included) directly to C
#pragma unroll
    for (int i = 0; i < MI; i++)
#pragma unroll
        for (int j = 0; j < NI; j++)
            wmma::store_matrix_sync(
                &C[(size_t)(m0 + warp_m * (BM / WR) + i * 16) * N +
                   n0 + warp_n * (BN / WC) + j * 16],
                acc[i][j], N, wmma::mem_row_major);
}

template <int BM, int BN, int WR, int WC>
__global__ __launch_bounds__(256) void gemm_wmma(
    const float* __restrict__ A, const float* __restrict__ W,
    const float* __restrict__ bias, float* __restrict__ C,
    int M, int N, int K)
{
    extern __shared__ float sm[];
    gemm_body<BM, BN, WR, WC>(A, W, bias, C, M, N, K,
                              blockIdx.y * BM, blockIdx.x * BN, sm);
}

// Batched Q/K/V projection: blockIdx.z selects the matrix set.
__global__ __launch_bounds__(256) void gemm_qkv_wmma(
    const float* __restrict__ q,  const float* __restrict__ k,
    const float* __restrict__ v,
    const float* __restrict__ wq, const float* __restrict__ wk,
    const float* __restrict__ wv,
    const float* __restrict__ bq, const float* __restrict__ bk,
    const float* __restrict__ bv,
    float* __restrict__ qp, float* __restrict__ kp, float* __restrict__ vp)
{
    extern __shared__ float sm[];
    const float *A, *W, *bias;
    float* C;
    if (blockIdx.z == 0)      { A = q; W = wq; bias = bq; C = qp; }
    else if (blockIdx.z == 1) { A = k; W = wk; bias = bk; C = kp; }
    else                      { A = v; W = wv; bias = bv; C = vp; }
    gemm_body<64, 128, 2, 4>(A, W, bias, C, BS_, DA_, DM_,
                             blockIdx.y * 64, blockIdx.x * 128, sm);
}

// =================================================================
// Logits+exp (R14 version): 256 threads, 64q x 32k tiles, pipelined
// across heads; xdiff in registers (head-invariant mapping).
// smem: Qt[2][64*68] Kt[2][32*68] xw[2048] Ls[8][320] = 70656 B.
// =================================================================
#define LOG_SMEM_BYTES 70656

__global__ __launch_bounds__(256) void logits_exp_wmma(
    const float* __restrict__ qp, const float* __restrict__ kp,
    const float* __restrict__ xs, const float* __restrict__ xdiff,
    float* __restrict__ attn, float* __restrict__ psum)
{
    constexpr int SQ = 64 * 68;   // 4352
    constexpr int SK = 32 * 68;   // 2176

    extern __shared__ float sm[];
    float* QtB = sm;                     // 2 stages
    float* KtB = sm + 2 * SQ;            // 2 stages
    float* xw  = sm + 2 * SQ + 2 * SK;   // 2048
    float* LsB = xw + 2048;              // 8 x 320

    const int tid  = threadIdx.x;
    const int w    = tid >> 5;
    const int lane = tid & 31;
    const int wq   = w & 3;     // q-group (16 rows)
    const int wkh  = w >> 2;    // k-half (16 cols)
    const int b  = blockIdx.z;
    const int q0 = blockIdx.y * 64;
    const int k0 = blockIdx.x * 32;
    float* Ls = LsB + w * 320;  // private 16x20

    auto loadQK = [&](int st, int h) {
        float* Qt = QtB + st * SQ;
        float* Kt = KtB + st * SK;
#pragma unroll
        for (int r = 0; r < 4; r++) {
            int idx = tid + 256 * r;
            int qi = idx >> 4, d4 = (idx & 15) * 4;
            cp16(&Qt[qi * 68 + d4],
                 &qp[(size_t)(b * S_ + q0 + qi) * DA_ + h * DEP_ + d4]);
        }
#pragma unroll
        for (int r = 0; r < 2; r++) {
            int idx = tid + 256 * r;
            int kk = idx >> 4, d4 = (idx & 15) * 4;
            cp16(&Kt[kk * 68 + d4],
                 &kp[(size_t)(b * S_ + k0 + kk) * DA_ + h * DEP_ + d4]);
        }
    };

    // xw tile (one-time, with head-0 group)
#pragma unroll
    for (int r = 0; r < 2; r++) {
        int idx = tid + 256 * r;
        int qi = idx >> 3, c4 = (idx & 7) * 4;
        cp16(&xw[qi * 32 + c4], &xs[(size_t)(b * S_ + q0 + qi) * 32 + c4]);
    }
    loadQK(0, 0);
    cp_commit();

    // xdiff -> registers (head-invariant per-thread mapping)
    float4 xdr[2][4];
    const float4* xdg = (const float4*)xdiff;
#pragma unroll
    for (int r = 0; r < 2; r++) {
        int idx = lane + 32 * r;
        int qi = idx >> 2, g = idx & 3;
        int qrow = wq * 16 + qi;
        int fcol = wkh * 16 + g * 4;
        const float4* src = &xdg[((size_t)(b * S_ + q0 + qrow)) * S_ + k0 + fcol];
#pragma unroll
        for (int t = 0; t < 4; t++) xdr[r][t] = src[t];
    }

    for (int h = 0; h < H_; h++) {
        if (h) __syncthreads();          // MMA(h-1) reads done before cp reuse
        if (h + 1 < H_) {
            loadQK((h + 1) & 1, h + 1);
            cp_commit();
            cp_wait<1>();
        } else {
            cp_wait<0>();
        }
        __syncthreads();                 // stage h visible

        float* Qt = QtB + (h & 1) * SQ;
        float* Kt = KtB + (h & 1) * SK;

        FragC acc;
        wmma::fill_fragment(acc, 0.0f);
#pragma unroll
        for (int ds = 0; ds < 8; ds++) {
            FragA a;
            wmma::load_matrix_sync(a, &Qt[(wq * 16) * 68 + ds * 8], 68);
            cvt_tf32(a);
            FragBc bf;
            wmma::load_matrix_sync(bf, &Kt[(wkh * 16) * 68 + ds * 8], 68);
            cvt_tf32(bf);
            wmma::mma_sync(acc, a, bf, acc);
        }

        wmma::store_matrix_sync(Ls, acc, 20, wmma::mem_row_major);
        __syncwarp();

#pragma unroll
        for (int r = 0; r < 2; r++) {
            int idx = lane + 32 * r;
            int qi = idx >> 2;
            int g  = idx & 3;
            int qrow = wq * 16 + qi;
            int fcol = wkh * 16 + g * 4;
            float4 lv = *(float4*)&Ls[qi * 20 + g * 4];
            float4 xh = *(float4*)&xw[qrow * 32 + h * 4];
            float e[4];
            float* lp = &lv.x;
            float tsum = 0.0f;
#pragma unroll
            for (int t = 0; t < 4; t++) {
                float4 xv = xdr[r][t];
                float bias = xv.x * xh.x + xv.y * xh.y + xv.z * xh.z + xv.w * xh.w;
                e[t] = __expf(lp[t] * 0.125f + bias * 0.5f);
                tsum += e[t];
            }
            size_t row_g = (size_t)(b * H_ + h) * S_ + q0 + qrow;
            *(float4*)&attn[row_g * S_ + k0 + fcol] =
                make_float4(e[0], e[1], e[2], e[3]);
            tsum += __shfl_down_sync(0xffffffffu, tsum, 2, 4);
            tsum += __shfl_down_sync(0xffffffffu, tsum, 1, 4);
            if ((lane & 3) == 0)
                psum[row_g * 128 + blockIdx.x * 2 + wkh] = tsum;
        }
    }
}

// =================================================================
// Row-sum reduce: g_rinv[row] = 1 / sum(g_psum[row][0..127])
// =================================================================
__global__ __launch_bounds__(256) void rowsum_kernel(
    const float* __restrict__ psum, float* __restrict__ rinv)
{
    const int wir  = threadIdx.x >> 5;
    const int lane = threadIdx.x & 31;
    const size_t row = (size_t)blockIdx.x * 8 + wir;
    const float* p = psum + row * 128;
    float s = (p[lane] + p[lane + 32]) + (p[lane + 64] + p[lane + 96]);
#pragma unroll
    for (int o = 16; o > 0; o >>= 1) s += __shfl_xor_sync(0xffffffffu, s, o);
    if (lane == 0) rinv[row] = 1.0f / s;
}

// =================================================================
// PV (R14 version), 3-stage ring, 64q tiles: ctx = (e @ V) * rinv ;
// writes p = e*rinv back to attn in place. Block = (64q, bh), BK=32.
// =================================================================
#define PV_SMEM_BYTES 54016

__global__ __launch_bounds__(256) void pv_wmma(
    float* __restrict__ attn, const float* __restrict__ vp,
    const float* __restrict__ rinv, float* __restrict__ ctx)
{
    constexpr int SA = 64 * 36;   // 2304
    constexpr int SV = 32 * 68;   // 2176

    extern __shared__ float sm[];
    float* AtB = sm;
    float* VtB = sm + 3 * SA;
    float* rs  = sm + 3 * SA + 3 * SV;   // [64]
    float* Cs  = sm;                     // epilogue reuse

    const int tid = threadIdx.x;
    const int w   = tid >> 5;
    const int wq  = w & 3;
    const int wd  = w >> 2;
    const int bh  = blockIdx.y;
    const int b   = bh >> 3, h = bh & 7;
    const int q0  = blockIdx.x * 64;
    const int nc  = S_ / 32;

    if (tid < 64) rs[tid] = rinv[(size_t)bh * S_ + q0 + tid];

    auto loadChunk = [&](int st, int c) {
        float* At = AtB + st * SA;
        float* Vt = VtB + st * SV;
#pragma unroll
        for (int r = 0; r < 2; r++) {
            int idx = tid + 256 * r;
            int qi = idx >> 3, k4 = (idx & 7) * 4;
            cp16(&At[qi * 36 + k4],
                 &attn[((size_t)bh * S_ + q0 + qi) * S_ + c * 32 + k4]);
        }
#pragma unroll
        for (int r = 0; r < 2; r++) {
            int idx = tid + 256 * r;
            int kk = idx >> 4, d4 = (idx & 15) * 4;
            cp16(&Vt[kk * 68 + d4],
                 &vp[(size_t)(b * S_ + c * 32 + kk) * DA_ + h * DEP_ + d4]);
        }
    };

    FragC acc[2];
#pragma unroll
    for (int j = 0; j < 2; j++) wmma::fill_fragment(acc[j], 0.0f);

    loadChunk(0, 0); cp_commit();
    loadChunk(1, 1); cp_commit();

    for (int c = 0; c < nc; c++) {
        if (c + 2 < nc) {
            loadChunk((c + 2) % 3, c + 2);
            cp_commit();
            cp_wait<2>();
        } else if (c + 1 < nc) {
            cp_wait<1>();
        } else {
            cp_wait<0>();
        }
        __syncthreads();

        const float* At = AtB + (c % 3) * SA;
        const float* Vt = VtB + (c % 3) * SV;

        // write p = e * rinv back to attn
#pragma unroll
        for (int r = 0; r < 2; r++) {
            int idx = tid + 256 * r;
            int qi = idx >> 3, k4 = (idx & 7) * 4;
            float4 v = *(const float4*)&At[qi * 36 + k4];
            float riv = rs[qi];
            v.x *= riv; v.y *= riv; v.z *= riv; v.w *= riv;
            *(float4*)&attn[((size_t)bh * S_ + q0 + qi) * S_ + c * 32 + k4] = v;
        }

#pragma unroll
        for (int ds = 0; ds < 4; ds++) {
            FragA a;
            wmma::load_matrix_sync(a, &At[(wq * 16) * 36 + ds * 8], 36);
            cvt_tf32(a);
#pragma unroll
            for (int j = 0; j < 2; j++) {
                FragB bf;
                wmma::load_matrix_sync(bf, &Vt[ds * 8 * 68 + wd * 32 + j * 16], 68);
                cvt_tf32(bf);
                wmma::mma_sync(acc[j], a, bf, acc[j]);
            }
        }
        __syncthreads();
    }

    // epilogue: stage in smem, scale by rinv, store
#pragma unroll
    for (int j = 0; j < 2; j++)
        wmma::store_matrix_sync(&Cs[(wq * 16) * 68 + wd * 32 + j * 16],
                                acc[j], 68, wmma::mem_row_major);
    __syncthreads();

#pragma unroll
    for (int r = 0; r < 4; r++) {
        int idx = tid + 256 * r;
        int qi = idx >> 4, d4 = (idx & 15) * 4;
        float4 v = *(float4*)&Cs[qi * 68 + d4];
        float riv = rs[qi];
        v.x *= riv; v.y *= riv; v.z *= riv; v.w *= riv;
        *(float4*)&ctx[(size_t)(b * S_ + q0 + qi) * DA_ + h * DEP_ + d4] = v;
    }
}

// =================================================================
extern "C" void kernel_launch(void* const* d_in, const int* in_sizes, int n_in,
                              void* d_out, int out_size)
{
    const float* q     = (const float*)d_in[0];
    const float* k     = (const float*)d_in[1];
    const float* v     = (const float*)d_in[2];
    const float* xdiff = (const float*)d_in[3];
    const float* wq    = (const float*)d_in[4];
    const float* bq    = (const float*)d_in[5];
    const float* wk    = (const float*)d_in[6];
    const float* bk    = (const float*)d_in[7];
    const float* wv    = (const float*)d_in[8];
    const float* bv    = (const float*)d_in[9];
    const float* wx    = (const float*)d_in[10];
    const float* bx    = (const float*)d_in[11];
    const float* wo    = (const float*)d_in[12];
    const float* bo    = (const float*)d_in[13];

    float* out  = (float*)d_out;                        // [B,S,DM]
    float* attn = out + (size_t)BS_ * DM_;              // [B,H,S,S]

    float *qp, *kp, *vp, *xs, *ctx, *psum, *rinv;
    cudaGetSymbolAddress((void**)&qp,   g_qp);
    cudaGetSymbolAddress((void**)&kp,   g_kp);
    cudaGetSymbolAddress((void**)&vp,   g_vp);
    cudaGetSymbolAddress((void**)&xs,   g_xs);
    cudaGetSymbolAddress((void**)&ctx,  g_ctx);
    cudaGetSymbolAddress((void**)&psum, g_psum);
    cudaGetSymbolAddress((void**)&rinv, g_rinv);

    const int SM_G128 = (3 * 64 * 36 + 3 * 32 * 132) * 4;    // 78336
    const int SM_G32  = (3 * 64 * 36 + 3 * 32 * 36) * 4;     // 41472
    const int SM_LOG  = LOG_SMEM_BYTES;                      // 70656
    const int SM_PV   = PV_SMEM_BYTES;                       // 54016

    cudaFuncSetAttribute((const void*)gemm_qkv_wmma,
                         cudaFuncAttributeMaxDynamicSharedMemorySize, SM_G128);
    cudaFuncSetAttribute((const void*)gemm_wmma<64, 128, 2, 4>,
                         cudaFuncAttributeMaxDynamicSharedMemorySize, SM_G128);
    cudaFuncSetAttribute((const void*)gemm_wmma<64, 32, 4, 2>,
                         cudaFuncAttributeMaxDynamicSharedMemorySize, SM_G32);
    cudaFuncSetAttribute((const void*)logits_exp_wmma,
                         cudaFuncAttributeMaxDynamicSharedMemorySize, SM_LOG);
    cudaFuncSetAttribute((const void*)pv_wmma,
                         cudaFuncAttributeMaxDynamicSharedMemorySize, SM_PV);

    // Q/K/V projections — one batched launch
    gemm_qkv_wmma<<<dim3(DA_ / 128, BS_ / 64, 3), 256, SM_G128>>>(
        q, k, v, wq, wk, wv, bq, bk, bv, qp, kp, vp);

    // x = qp @ wx + bx
    gemm_wmma<64, 32, 4, 2><<<dim3(1, BS_ / 64), 256, SM_G32>>>(
        qp, wx, bx, xs, BS_, H_ * F_, DA_);

    // logits + bias + exp -> attn (unnormalized) + partial sums
    logits_exp_wmma<<<dim3(S_ / 32, S_ / 64, B_), 256, SM_LOG>>>(
        qp, kp, xs, xdiff, attn, psum);

    // rowsum -> 1/s
    rowsum_kernel<<<ROWS_ / 8, 256>>>(psum, rinv);

    // PV + in-place normalization of attn
    pv_wmma<<<dim3(S_ / 64, B_ * H_), 256, SM_PV>>>(attn, vp, rinv, ctx);

    // out = ctx @ wo + bo
    gemm_wmma<64, 128, 2, 4><<<dim3(DM_ / 128, BS_ / 64), 256, SM_G128>>>(
        ctx, wo, bo, out, BS_, DM_, DA_);
}

// round 17
// speedup vs baseline: 1.0773x; 1.0016x over previous
#include <cuda_runtime.h>
#include <mma.h>
#include <cstdint>
#include <cstddef>

using namespace nvcuda;

// Problem dims
#define B_ 4
#define S_ 2048
#define DM_ 512
#define DA_ 512
#define H_ 8
#define F_ 4
#define DEP_ 64
#define BS_ (B_ * S_)         // 8192
#define ROWS_ (B_ * H_ * S_)  // 65536

// ---------------- scratch (no allocations allowed) ----------------
__device__ float g_qp[(size_t)BS_ * DA_];
__device__ float g_kp[(size_t)BS_ * DA_];
__device__ float g_vp[(size_t)BS_ * DA_];
__device__ float g_xs[(size_t)BS_ * (H_ * F_)];
__device__ float g_ctx[(size_t)BS_ * DA_];
__device__ float g_psum[(size_t)ROWS_ * 128];
__device__ float g_rinv[(size_t)ROWS_];

typedef wmma::fragment<wmma::matrix_a, 16, 16, 8, wmma::precision::tf32, wmma::row_major> FragA;
typedef wmma::fragment<wmma::matrix_b, 16, 16, 8, wmma::precision::tf32, wmma::row_major> FragB;
typedef wmma::fragment<wmma::matrix_b, 16, 16, 8, wmma::precision::tf32, wmma::col_major> FragBc;
typedef wmma::fragment<wmma::accumulator, 16, 16, 8, float> FragC;

template <typename F>
__device__ __forceinline__ void cvt_tf32(F& f) {
#pragma unroll
    for (int i = 0; i < f.num_elements; i++)
        f.x[i] = wmma::__float_to_tf32(f.x[i]);
}

// ---------------- cp.async helpers ----------------
__device__ __forceinline__ void cp16(float* dst_smem, const float* src_g) {
    uint32_t d = (uint32_t)__cvta_generic_to_shared(dst_smem);
    asm volatile("cp.async.cg.shared.global [%0], [%1], 16;"
                 :: "r"(d), "l"(src_g) : "memory");
}
__device__ __forceinline__ void cp_commit() {
    asm volatile("cp.async.commit_group;" ::: "memory");
}
template <int N>
__device__ __forceinline__ void cp_wait() {
    asm volatile("cp.async.wait_group %0;" :: "n"(N) : "memory");
}

// =================================================================
// Shared GEMM device body (R14 pipeline ordering):
// C[M,N] = A[M,K] @ W[K,N] + bias[N]; BM x BN tile, BK=32, 3-stage.
// Bias pre-loaded into accumulator fragments; epilogue stores the
// accumulators DIRECTLY to global (no smem staging, no extra syncs).
// =================================================================
template <int BM, int BN, int WR, int WC>
__device__ __forceinline__ void gemm_body(
    const float* __restrict__ A, const float* __restrict__ W,
    const float* __restrict__ bias, float* __restrict__ C,
    int M, int N, int K, int m0, int n0, float* sm)
{
    constexpr int LDA = 36;
    constexpr int LDB = BN + 4;
    constexpr int SA  = BM * LDA;
    constexpr int SW  = 32 * LDB;
    constexpr int MI = BM / (WR * 16);
    constexpr int NI = BN / (WC * 16);

    const int tid = threadIdx.x;
    const int wid = tid >> 5;
    const int warp_m = wid % WR;
    const int warp_n = wid / WR;
    const int nc = K / 32;

    // ---- bias -> accumulator fragments (once, before stage preload) ----
    FragC acc[MI][NI];
    {
        float* bs = sm;   // 16 rows x BN, stride LDB (reuses stage area)
        for (int idx = tid; idx < 4 * BN; idx += 256) {   // 16*BN/4 float4
            int row = idx / (BN / 4), n4 = (idx % (BN / 4)) * 4;
            *(float4*)&bs[row * LDB + n4] = *(const float4*)&bias[n0 + n4];
        }
        __syncthreads();
#pragma unroll
        for (int j = 0; j < NI; j++)
            wmma::load_matrix_sync(acc[0][j],
                &bs[warp_n * (BN / WC) + j * 16], LDB, wmma::mem_row_major);
#pragma unroll
        for (int i = 1; i < MI; i++)
#pragma unroll
            for (int j = 0; j < NI; j++) acc[i][j] = acc[0][j];
        __syncthreads();   // before stage preloads overwrite bs
    }

    auto loadStage = [&](int st, int c) {
        float* As = sm + st * SA;
        float* Ws = sm + 3 * SA + st * SW;
#pragma unroll
        for (int r = 0; r < BM / 32; r++) {
            int idx = tid + 256 * r;
            int m = idx >> 3, k4 = (idx & 7) * 4;
            cp16(&As[m * LDA + k4], &A[(size_t)(m0 + m) * K + c * 32 + k4]);
        }
#pragma unroll
        for (int r = 0; r < BN / 32; r++) {
            int idx = tid + 256 * r;
            int kk = idx / (BN / 4), n4 = (idx % (BN / 4)) * 4;
            cp16(&Ws[kk * LDB + n4], &W[(size_t)(c * 32 + kk) * N + n0 + n4]);
        }
    };

    loadStage(0, 0); cp_commit();
    loadStage(1, 1); cp_commit();

    for (int c = 0; c < nc; c++) {
        if (c + 2 < nc) {
            loadStage((c + 2) % 3, c + 2);
            cp_commit();
            cp_wait<2>();
        } else if (c + 1 < nc) {
            cp_wait<1>();
        } else {
            cp_wait<0>();
        }
        __syncthreads();

        const float* As = sm + (c % 3) * SA;
        const float* Ws = sm + 3 * SA + (c % 3) * SW;
#pragma unroll
        for (int ds = 0; ds < 4; ds++) {
            FragA af[MI];
#pragma unroll
            for (int i = 0; i < MI; i++) {
                wmma::load_matrix_sync(af[i],
                    &As[(warp_m * (BM / WR) + i * 16) * LDA + ds * 8], LDA);
                cvt_tf32(af[i]);
            }
            FragB bf;
#pragma unroll
            for (int j = 0; j < NI; j++) {
                wmma::load_matrix_sync(bf,
                    &Ws[ds * 8 * LDB + warp_n * (BN / WC) + j * 16], LDB);
                cvt_tf32(bf);
#pragma unroll
                for (int i = 0; i < MI; i++)
                    wmma::mma_sync(acc[i][j], af[i], bf, acc[i][j]);
            }
        }
        __syncthreads();
    }

    // epilogue: store accumulators (bias already included) directly to C
#pragma unroll
    for (int i = 0; i < MI; i++)
#pragma unroll
        for (int j = 0; j < NI; j++)
            wmma::store_matrix_sync(
                &C[(size_t)(m0 + warp_m * (BM / WR) + i * 16) * N +
                   n0 + warp_n * (BN / WC) + j * 16],
                acc[i][j], N, wmma::mem_row_major);
}

template <int BM, int BN, int WR, int WC>
__global__ __launch_bounds__(256) void gemm_wmma(
    const float* __restrict__ A, const float* __restrict__ W,
    const float* __restrict__ bias, float* __restrict__ C,
    int M, int N, int K)
{
    extern __shared__ float sm[];
    gemm_body<BM, BN, WR, WC>(A, W, bias, C, M, N, K,
                              blockIdx.y * BM, blockIdx.x * BN, sm);
}

// Batched Q/K/V projection: blockIdx.z selects the matrix set.
__global__ __launch_bounds__(256) void gemm_qkv_wmma(
    const float* __restrict__ q,  const float* __restrict__ k,
    const float* __restrict__ v,
    const float* __restrict__ wq, const float* __restrict__ wk,
    const float* __restrict__ wv,
    const float* __restrict__ bq, const float* __restrict__ bk,
    const float* __restrict__ bv,
    float* __restrict__ qp, float* __restrict__ kp, float* __restrict__ vp)
{
    extern __shared__ float sm[];
    const float *A, *W, *bias;
    float* C;
    if (blockIdx.z == 0)      { A = q; W = wq; bias = bq; C = qp; }
    else if (blockIdx.z == 1) { A = k; W = wk; bias = bk; C = kp; }
    else                      { A = v; W = wv; bias = bv; C = vp; }
    gemm_body<64, 128, 2, 4>(A, W, bias, C, BS_, DA_, DM_,
                             blockIdx.y * 64, blockIdx.x * 128, sm);
}

// =================================================================
// Logits+exp: 256 threads, 64q x 32k tiles, 3-STAGE head ring
// (two heads' loads in flight; R14 load-before-wait ordering).
// xdiff in registers (head-invariant mapping).
// smem: Qt[3][64*68] Kt[3][32*68] xw[2048] Ls[8][320] = 96768 B
// -> 2 blocks/SM.
// =================================================================
#define LOG_SMEM_BYTES 96768

__global__ __launch_bounds__(256) void logits_exp_wmma(
    const float* __restrict__ qp, const float* __restrict__ kp,
    const float* __restrict__ xs, const float* __restrict__ xdiff,
    float* __restrict__ attn, float* __restrict__ psum)
{
    constexpr int SQ = 64 * 68;   // 4352
    constexpr int SK = 32 * 68;   // 2176

    extern __shared__ float sm[];
    float* QtB = sm;                     // 3 stages
    float* KtB = sm + 3 * SQ;            // 3 stages
    float* xw  = sm + 3 * SQ + 3 * SK;   // 2048
    float* LsB = xw + 2048;              // 8 x 320

    const int tid  = threadIdx.x;
    const int w    = tid >> 5;
    const int lane = tid & 31;
    const int wq   = w & 3;     // q-group (16 rows)
    const int wkh  = w >> 2;    // k-half (16 cols)
    const int b  = blockIdx.z;
    const int q0 = blockIdx.y * 64;
    const int k0 = blockIdx.x * 32;
    float* Ls = LsB + w * 320;  // private 16x20

    auto loadQK = [&](int st, int h) {
        float* Qt = QtB + st * SQ;
        float* Kt = KtB + st * SK;
#pragma unroll
        for (int r = 0; r < 4; r++) {
            int idx = tid + 256 * r;
            int qi = idx >> 4, d4 = (idx & 15) * 4;
            cp16(&Qt[qi * 68 + d4],
                 &qp[(size_t)(b * S_ + q0 + qi) * DA_ + h * DEP_ + d4]);
        }
#pragma unroll
        for (int r = 0; r < 2; r++) {
            int idx = tid + 256 * r;
            int kk = idx >> 4, d4 = (idx & 15) * 4;
            cp16(&Kt[kk * 68 + d4],
                 &kp[(size_t)(b * S_ + k0 + kk) * DA_ + h * DEP_ + d4]);
        }
    };

    // xw tile (one-time, with head-0 group)
#pragma unroll
    for (int r = 0; r < 2; r++) {
        int idx = tid + 256 * r;
        int qi = idx >> 3, c4 = (idx & 7) * 4;
        cp16(&xw[qi * 32 + c4], &xs[(size_t)(b * S_ + q0 + qi) * 32 + c4]);
    }
    loadQK(0, 0);
    cp_commit();
    loadQK(1, 1);
    cp_commit();

    // xdiff -> registers (head-invariant per-thread mapping)
    float4 xdr[2][4];
    const float4* xdg = (const float4*)xdiff;
#pragma unroll
    for (int r = 0; r < 2; r++) {
        int idx = lane + 32 * r;
        int qi = idx >> 2, g = idx & 3;
        int qrow = wq * 16 + qi;
        int fcol = wkh * 16 + g * 4;
        const float4* src = &xdg[((size_t)(b * S_ + q0 + qrow)) * S_ + k0 + fcol];
#pragma unroll
        for (int t = 0; t < 4; t++) xdr[r][t] = src[t];
    }

    for (int h = 0; h < H_; h++) {
        if (h) __syncthreads();          // compute(h-1) done: its stage may be reused
        if (h + 2 < H_) {
            loadQK((h + 2) % 3, h + 2);  // overwrites stage used by compute(h-1)
            cp_commit();
            cp_wait<2>();                // stage h landed; h+1, h+2 may be in flight
        } else if (h + 1 < H_) {
            cp_wait<1>();
        } else {
            cp_wait<0>();
        }
        __syncthreads();                 // stage h visible to all warps

        float* Qt = QtB + (h % 3) * SQ;
        float* Kt = KtB + (h % 3) * SK;

        FragC acc;
        wmma::fill_fragment(acc, 0.0f);
#pragma unroll
        for (int ds = 0; ds < 8; ds++) {
            FragA a;
            wmma::load_matrix_sync(a, &Qt[(wq * 16) * 68 + ds * 8], 68);
            cvt_tf32(a);
            FragBc bf;
            wmma::load_matrix_sync(bf, &Kt[(wkh * 16) * 68 + ds * 8], 68);
            cvt_tf32(bf);
            wmma::mma_sync(acc, a, bf, acc);
        }

        wmma::store_matrix_sync(Ls, acc, 20, wmma::mem_row_major);
        __syncwarp();

#pragma unroll
        for (int r = 0; r < 2; r++) {
            int idx = lane + 32 * r;
            int qi = idx >> 2;
            int g  = idx & 3;
            int qrow = wq * 16 + qi;
            int fcol = wkh * 16 + g * 4;
            float4 lv = *(float4*)&Ls[qi * 20 + g * 4];
            float4 xh = *(float4*)&xw[qrow * 32 + h * 4];
            float e[4];
            float* lp = &lv.x;
            float tsum = 0.0f;
#pragma unroll
            for (int t = 0; t < 4; t++) {
                float4 xv = xdr[r][t];
                float bias = xv.x * xh.x + xv.y * xh.y + xv.z * xh.z + xv.w * xh.w;
                e[t] = __expf(lp[t] * 0.125f + bias * 0.5f);
                tsum += e[t];
            }
            size_t row_g = (size_t)(b * H_ + h) * S_ + q0 + qrow;
            *(float4*)&attn[row_g * S_ + k0 + fcol] =
                make_float4(e[0], e[1], e[2], e[3]);
            tsum += __shfl_down_sync(0xffffffffu, tsum, 2, 4);
            tsum += __shfl_down_sync(0xffffffffu, tsum, 1, 4);
            if ((lane & 3) == 0)
                psum[row_g * 128 + blockIdx.x * 2 + wkh] = tsum;
        }
    }
}

// =================================================================
// Row-sum reduce: g_rinv[row] = 1 / sum(g_psum[row][0..127])
// =================================================================
__global__ __launch_bounds__(256) void rowsum_kernel(
    const float* __restrict__ psum, float* __restrict__ rinv)
{
    const int wir  = threadIdx.x >> 5;
    const int lane = threadIdx.x & 31;
    const size_t row = (size_t)blockIdx.x * 8 + wir;
    const float* p = psum + row * 128;
    float s = (p[lane] + p[lane + 32]) + (p[lane + 64] + p[lane + 96]);
#pragma unroll
    for (int o = 16; o > 0; o >>= 1) s += __shfl_xor_sync(0xffffffffu, s, o);
    if (lane == 0) rinv[row] = 1.0f / s;
}

// =================================================================
// PV (R14/R16 version), 3-stage ring, 64q tiles: ctx = (e @ V)*rinv;
// writes p = e*rinv back to attn in place. Block = (64q, bh), BK=32.
// =================================================================
#define PV_SMEM_BYTES 54016

__global__ __launch_bounds__(256) void pv_wmma(
    float* __restrict__ attn, const float* __restrict__ vp,
    const float* __restrict__ rinv, float* __restrict__ ctx)
{
    constexpr int SA = 64 * 36;   // 2304
    constexpr int SV = 32 * 68;   // 2176

    extern __shared__ float sm[];
    float* AtB = sm;
    float* VtB = sm + 3 * SA;
    float* rs  = sm + 3 * SA + 3 * SV;   // [64]
    float* Cs  = sm;                     // epilogue reuse

    const int tid = threadIdx.x;
    const int w   = tid >> 5;
    const int wq  = w & 3;
    const int wd  = w >> 2;
    const int bh  = blockIdx.y;
    const int b   = bh >> 3, h = bh & 7;
    const int q0  = blockIdx.x * 64;
    const int nc  = S_ / 32;

    if (tid < 64) rs[tid] = rinv[(size_t)bh * S_ + q0 + tid];

    auto loadChunk = [&](int st, int c) {
        float* At = AtB + st * SA;
        float* Vt = VtB + st * SV;
#pragma unroll
        for (int r = 0; r < 2; r++) {
            int idx = tid + 256 * r;
            int qi = idx >> 3, k4 = (idx & 7) * 4;
            cp16(&At[qi * 36 + k4],
                 &attn[((size_t)bh * S_ + q0 + qi) * S_ + c * 32 + k4]);
        }
#pragma unroll
        for (int r = 0; r < 2; r++) {
            int idx = tid + 256 * r;
            int kk = idx >> 4, d4 = (idx & 15) * 4;
            cp16(&Vt[kk * 68 + d4],
                 &vp[(size_t)(b * S_ + c * 32 + kk) * DA_ + h * DEP_ + d4]);
        }
    };

    FragC acc[2];
#pragma unroll
    for (int j = 0; j < 2; j++) wmma::fill_fragment(acc[j], 0.0f);

    loadChunk(0, 0); cp_commit();
    loadChunk(1, 1); cp_commit();

    for (int c = 0; c < nc; c++) {
        if (c + 2 < nc) {
            loadChunk((c + 2) % 3, c + 2);
            cp_commit();
            cp_wait<2>();
        } else if (c + 1 < nc) {
            cp_wait<1>();
        } else {
            cp_wait<0>();
        }
        __syncthreads();

        const float* At = AtB + (c % 3) * SA;
        const float* Vt = VtB + (c % 3) * SV;

        // write p = e * rinv back to attn
#pragma unroll
        for (int r = 0; r < 2; r++) {
            int idx = tid + 256 * r;
            int qi = idx >> 3, k4 = (idx & 7) * 4;
            float4 v = *(const float4*)&At[qi * 36 + k4];
            float riv = rs[qi];
            v.x *= riv; v.y *= riv; v.z *= riv; v.w *= riv;
            *(float4*)&attn[((size_t)bh * S_ + q0 + qi) * S_ + c * 32 + k4] = v;
        }

#pragma unroll
        for (int ds = 0; ds < 4; ds++) {
            FragA a;
            wmma::load_matrix_sync(a, &At[(wq * 16) * 36 + ds * 8], 36);
            cvt_tf32(a);
#pragma unroll
            for (int j = 0; j < 2; j++) {
                FragB bf;
                wmma::load_matrix_sync(bf, &Vt[ds * 8 * 68 + wd * 32 + j * 16], 68);
                cvt_tf32(bf);
                wmma::mma_sync(acc[j], a, bf, acc[j]);
            }
        }
        __syncthreads();
    }

    // epilogue: stage in smem, scale by rinv, store
#pragma unroll
    for (int j = 0; j < 2; j++)
        wmma::store_matrix_sync(&Cs[(wq * 16) * 68 + wd * 32 + j * 16],
                                acc[j], 68, wmma::mem_row_major);
    __syncthreads();

#pragma unroll
    for (int r = 0; r < 4; r++) {
        int idx = tid + 256 * r;
        int qi = idx >> 4, d4 = (idx & 15) * 4;
        float4 v = *(float4*)&Cs[qi * 68 + d4];
        float riv = rs[qi];
        v.x *= riv; v.y *= riv; v.z *= riv; v.w *= riv;
        *(float4*)&ctx[(size_t)(b * S_ + q0 + qi) * DA_ + h * DEP_ + d4] = v;
    }
}

// =================================================================
extern "C" void kernel_launch(void* const* d_in, const int* in_sizes, int n_in,
                              void* d_out, int out_size)
{
    const float* q     = (const float*)d_in[0];
    const float* k     = (const float*)d_in[1];
    const float* v     = (const float*)d_in[2];
    const float* xdiff = (const float*)d_in[3];
    const float* wq    = (const float*)d_in[4];
    const float* bq    = (const float*)d_in[5];
    const float* wk    = (const float*)d_in[6];
    const float* bk    = (const float*)d_in[7];
    const float* wv    = (const float*)d_in[8];
    const float* bv    = (const float*)d_in[9];
    const float* wx    = (const float*)d_in[10];
    const float* bx    = (const float*)d_in[11];
    const float* wo    = (const float*)d_in[12];
    const float* bo    = (const float*)d_in[13];

    float* out  = (float*)d_out;                        // [B,S,DM]
    float* attn = out + (size_t)BS_ * DM_;              // [B,H,S,S]

    float *qp, *kp, *vp, *xs, *ctx, *psum, *rinv;
    cudaGetSymbolAddress((void**)&qp,   g_qp);
    cudaGetSymbolAddress((void**)&kp,   g_kp);
    cudaGetSymbolAddress((void**)&vp,   g_vp);
    cudaGetSymbolAddress((void**)&xs,   g_xs);
    cudaGetSymbolAddress((void**)&ctx,  g_ctx);
    cudaGetSymbolAddress((void**)&psum, g_psum);
    cudaGetSymbolAddress((void**)&rinv, g_rinv);

    const int SM_G128 = (3 * 64 * 36 + 3 * 32 * 132) * 4;    // 78336
    const int SM_G32  = (3 * 64 * 36 + 3 * 32 * 36) * 4;     // 41472
    const int SM_LOG  = LOG_SMEM_BYTES;                      // 96768
    const int SM_PV   = PV_SMEM_BYTES;                       // 54016

    cudaFuncSetAttribute((const void*)gemm_qkv_wmma,
                         cudaFuncAttributeMaxDynamicSharedMemorySize, SM_G128);
    cudaFuncSetAttribute((const void*)gemm_wmma<64, 128, 2, 4>,
                         cudaFuncAttributeMaxDynamicSharedMemorySize, SM_G128);
    cudaFuncSetAttribute((const void*)gemm_wmma<64, 32, 4, 2>,
                         cudaFuncAttributeMaxDynamicSharedMemorySize, SM_G32);
    cudaFuncSetAttribute((const void*)logits_exp_wmma,
                         cudaFuncAttributeMaxDynamicSharedMemorySize, SM_LOG);
    cudaFuncSetAttribute((const void*)pv_wmma,
                         cudaFuncAttributeMaxDynamicSharedMemorySize, SM_PV);

    // Q/K/V projections — one batched launch
    gemm_qkv_wmma<<<dim3(DA_ / 128, BS_ / 64, 3), 256, SM_G128>>>(
        q, k, v, wq, wk, wv, bq, bk, bv, qp, kp, vp);

    // x = qp @ wx + bx
    gemm_wmma<64, 32, 4, 2><<<dim3(1, BS_ / 64), 256, SM_G32>>>(
        qp, wx, bx, xs, BS_, H_ * F_, DA_);

    // logits + bias + exp -> attn (unnormalized) + partial sums
    logits_exp_wmma<<<dim3(S_ / 32, S_ / 64, B_), 256, SM_LOG>>>(
        qp, kp, xs, xdiff, attn, psum);

    // rowsum -> 1/s
    rowsum_kernel<<<ROWS_ / 8, 256>>>(psum, rinv);

    // PV + in-place normalization of attn
    pv_wmma<<<dim3(S_ / 64, B_ * H_), 256, SM_PV>>>(attn, vp, rinv, ctx);

    // out = ctx @ wo + bo
    gemm_wmma<64, 128, 2, 4><<<dim3(DM_ / 128, BS_ / 64), 256, SM_G128>>>(
        ctx, wo, bo, out, BS_, DM_, DA_);
}